// round 13
// baseline (speedup 1.0000x reference)
#include <cuda_runtime.h>
#include <cuda_bf16.h>

// InternalCoordinateTransform — flat, smem-free, SINGLE kernel (no prep).
// z_mat row r = (r+3, r+2, r+1, r): row r reads atoms r..r+3 (floats
// 3r..3r+11), writes floats 3r+9..3r+11.
// One THREAD per (batch, group): thread g handles rows 4g..4g+3 so the six
// param arrays are read as NATURALLY ALIGNED float4 at index g (no prep
// kernel, no shuffle, no scalar gathers). 1/sigma via inline MUFU rcp.
// x reads: floats 12g..12g+23 = 6 aligned LDG.128 (covers atoms 4g..4g+6).
// writes: floats 12g+9..12g+20 = STG.32 + STG.64 + 2x STG.128 + STG.32
// (warp tiles contiguous memory; L2 merges sectors).
// Row 2496 rides on the g==623 thread (its data = a[12..23], already loaded).
// Head floats 0..8 + row 0 handled by g==0 (registers only).
// Lessons: R4 no reg cap; R11 no 30KB-smem block design (wave quantization);
// R12 flat grid = best issue utilization.

#define NDIM    7500
#define NGROUPS 624           // rows 4g..4g+3, g<624 => rows 0..2495; row 2496 extra
#define PI_F    3.14159265358979f
#define TWO_PI  6.28318530717959f

__device__ __forceinline__ float rsqrt_ap(float x) {
    float r; asm("rsqrt.approx.f32 %0, %1;" : "=f"(r) : "f"(x)); return r;
}
__device__ __forceinline__ float sqrt_ap(float x) {
    float r; asm("sqrt.approx.f32 %0, %1;" : "=f"(r) : "f"(x)); return r;
}
__device__ __forceinline__ float rcp_ap(float x) {
    float r; asm("rcp.approx.f32 %0, %1;" : "=f"(r) : "f"(x)); return r;
}

// Hastings-style acos, |err| ~1e-7 rad, x in [-1,1].
__device__ __forceinline__ float acos_fast(float x) {
    float xa = fabsf(x);
    float p = -0.0012624911f;
    p = fmaf(p, xa,  0.0066700901f);
    p = fmaf(p, xa, -0.0170881256f);
    p = fmaf(p, xa,  0.0308918810f);
    p = fmaf(p, xa, -0.0501743046f);
    p = fmaf(p, xa,  0.0889789874f);
    p = fmaf(p, xa, -0.2145988016f);
    p = fmaf(p, xa,  1.5707963050f);
    float r = sqrt_ap(1.0f - xa) * p;
    return (x >= 0.0f) ? r : (PI_F - r);
}

// Full-quadrant atan2, |err| ~ few e-6 rad.
__device__ __forceinline__ float atan2_fast(float y, float x) {
    float ax = fabsf(x), ay = fabsf(y);
    float mx = fmaxf(fmaxf(ax, ay), 1e-35f);
    float mn = fminf(ax, ay);
    float t  = mn * rcp_ap(mx);
    float s  = t * t;
    float p = -0.01172120f;
    p = fmaf(p, s,  0.05265332f);
    p = fmaf(p, s, -0.11643287f);
    p = fmaf(p, s,  0.19354346f);
    p = fmaf(p, s, -0.33262347f);
    p = fmaf(p, s,  0.99997726f);
    float r = t * p;
    if (ay > ax)   r = 1.57079632679f - r;
    if (x < 0.0f)  r = PI_F - r;
    return copysignf(r, y);
}

// One z-row from 12 consecutive floats:
// p3=a[0..2] (atom r), p2=a[3..5], p1=a[6..8], p4=a[9..11] (atom r+3)
__device__ __forceinline__ void ic_row(const float* a, float& bond, float& ang, float& dihe)
{
    float d21x = a[3]-a[6], d21y = a[4]-a[7], d21z = a[5]-a[8];
    float d41x = a[9]-a[6], d41y = a[10]-a[7], d41z = a[11]-a[8];
    float s21 = fmaf(d21x,d21x, fmaf(d21y,d21y, d21z*d21z));
    float s41 = fmaf(d41x,d41x, fmaf(d41y,d41y, d41z*d41z));
    float r21 = rsqrt_ap(s21), r41 = rsqrt_ap(s41);
    bond = s41 * r41;
    float dotc = fmaf(d21x,d41x, fmaf(d21y,d41y, d21z*d41z));
    float cosang = fminf(fmaxf(dotc*r21*r41, -1.0f), 1.0f);
    ang = acos_fast(cosang);
    float ux = d21x*r21, uy = d21y*r21, uz = d21z*r21;
    float b0x = a[0]-a[3], b0y = a[1]-a[4], b0z = a[2]-a[5];
    float db0 = fmaf(b0x,ux, fmaf(b0y,uy, b0z*uz));
    float vx = fmaf(-db0,ux,b0x), vy = fmaf(-db0,uy,b0y), vz = fmaf(-db0,uz,b0z);
    float db2 = fmaf(d41x,ux, fmaf(d41y,uy, d41z*uz));
    float wx = fmaf(-db2,ux,d41x), wy = fmaf(-db2,uy,d41y), wz = fmaf(-db2,uz,d41z);
    float xx = fmaf(vx,wx, fmaf(vy,wy, vz*wz));
    float cx = fmaf(uy,vz,-uz*vy), cy = fmaf(uz,vx,-ux*vz), cz = fmaf(ux,vy,-uy*vx);
    float yy = fmaf(cx,wx, fmaf(cy,wy, cz*wz));
    dihe = atan2_fast(yy, xx);
}

// normalize one row's (bond, angle, dihedral)
__device__ __forceinline__ void norm_row(float bond, float ang, float dihe,
                                         float mbv, float sbv, float mav, float sav,
                                         float mdv, float sdv,
                                         float& ob, float& oa, float& od)
{
    ob = (bond - mbv) * rcp_ap(sbv);
    oa = (ang  - mav) * rcp_ap(sav);
    float dd = dihe - mdv;
    dd = (dd < -PI_F) ? dd + TWO_PI : dd;
    dd = (dd >  PI_F) ? dd - TWO_PI : dd;
    od = dd * rcp_ap(sdv);
}

__global__ __launch_bounds__(128)
void ict_flat(const float* __restrict__ x,
              const float* __restrict__ mb, const float* __restrict__ sb,
              const float* __restrict__ ma, const float* __restrict__ sa,
              const float* __restrict__ md, const float* __restrict__ sd,
              float* __restrict__ out, int total)
{
    unsigned t = blockIdx.x * 128u + threadIdx.x;
    if (t >= (unsigned)total) return;
    unsigned b = t / NGROUPS;          // constant divisor -> mulhi
    unsigned g = t - b * NGROUPS;
    const size_t base = (size_t)b * NDIM;

    const float4* __restrict__ xin  = (const float4*)(x + base);
    float*        __restrict__ o    = out + base;
    float4*       __restrict__ outv = (float4*)o;

    // ---- x: floats 12g..12g+23 (atoms 4g..4g+7): 6 aligned LDG.128 ----
    float a[24];
#pragma unroll
    for (int q = 0; q < 6; q++) {
        float4 f = __ldg(xin + 3 * g + q);
        a[4*q] = f.x; a[4*q+1] = f.y; a[4*q+2] = f.z; a[4*q+3] = f.w;
    }

    // ---- params rows 4g..4g+3: 6 naturally-aligned LDG.128 ----
    float4 qmb = __ldg((const float4*)mb + g);
    float4 qsb = __ldg((const float4*)sb + g);
    float4 qma = __ldg((const float4*)ma + g);
    float4 qsa = __ldg((const float4*)sa + g);
    float4 qmd = __ldg((const float4*)md + g);
    float4 qsd = __ldg((const float4*)sd + g);
    const float* pmb = (const float*)&qmb; const float* psb = (const float*)&qsb;
    const float* pma = (const float*)&qma; const float* psa = (const float*)&qsa;
    const float* pmd = (const float*)&qmd; const float* psd = (const float*)&qsd;

    float res[12];
#pragma unroll
    for (int j = 0; j < 4; j++) {
        // row r = 4g+j: atoms r..r+3 start at local float 3j
        float bond, ang, dihe;
        ic_row(a + 3 * j, bond, ang, dihe);
        norm_row(bond, ang, dihe, pmb[j], psb[j], pma[j], psa[j], pmd[j], psd[j],
                 res[3*j], res[3*j+1], res[3*j+2]);
    }

    // ---- stores: floats 12g+9 .. 12g+20 ----
    if (g == 0) {
        // head floats 0..8 are a copy of x; combine with row-0 results
        outv[0] = make_float4(a[0], a[1], a[2],  a[3]);
        outv[1] = make_float4(a[4], a[5], a[6],  a[7]);
        outv[2] = make_float4(a[8], res[0], res[1], res[2]);
    } else {
        o[12*g + 9] = res[0];
        *(float2*)(o + 12*g + 10) = make_float2(res[1], res[2]);   // 12g+10 even -> 8B aligned
    }
    outv[3*g + 3] = make_float4(res[3], res[4], res[5],  res[6]);
    outv[3*g + 4] = make_float4(res[7], res[8], res[9],  res[10]);
    o[12*g + 20] = res[11];

    // ---- row 2496 rides on g==623 (atoms 2496..2499 = a[12..23]) ----
    if (g == NGROUPS - 1) {
        float bond, ang, dihe;
        ic_row(a + 12, bond, ang, dihe);
        float ob, oa, od;
        norm_row(bond, ang, dihe,
                 __ldg(mb + 2496), __ldg(sb + 2496),
                 __ldg(ma + 2496), __ldg(sa + 2496),
                 __ldg(md + 2496), __ldg(sd + 2496), ob, oa, od);
        o[7497] = ob;
        *(float2*)(o + 7498) = make_float2(oa, od);                // 7498 even -> 8B aligned
    }
}

extern "C" void kernel_launch(void* const* d_in, const int* in_sizes, int n_in,
                              void* d_out, int out_size)
{
    const float* x  = (const float*)d_in[0];
    const float* mb = (const float*)d_in[2];
    const float* sb = (const float*)d_in[3];
    const float* ma = (const float*)d_in[4];
    const float* sa = (const float*)d_in[5];
    const float* md = (const float*)d_in[6];
    const float* sd = (const float*)d_in[7];

    int bsz   = in_sizes[0] / NDIM;     // 2048
    int total = bsz * NGROUPS;          // 1,277,952 threads (exactly 9984 blocks)

    ict_flat<<<(total + 127) / 128, 128>>>(x, mb, sb, ma, sa, md, sd,
                                           (float*)d_out, total);
}